// round 7
// baseline (speedup 1.0000x reference)
#include <cuda_runtime.h>
#include <cuda_bf16.h>

#define T_ 128
#define B_ 512
#define D_ 500
#define D4_ 125   // D/4 float4 per row
#define PF 16     // prefetch depth (rows ahead)

// Scratch (no allocation allowed): control-plane metadata.
// g_meta[b*T_+t]: bit0 = token t valid; bits[1:15] = (seg_to_emit_after_t + 1), 0 = none.
__device__ unsigned short g_meta[B_ * T_];
__device__ int g_newlen[B_];

// ---------------------------------------------------------------------------
// Kernel 1: per-column greedy packing scan (control plane).
// One block (128 threads) per batch column. Threads gather token lengths in
// parallel; lane 0 bulk-loads them into registers and runs a branchless
// greedy scan (unroll 8 only: keeps the loop body ~2KB, resident in L0 I$ —
// a fully-unrolled 20KB body thrashed L0 and serialized on I-fetch).
// ---------------------------------------------------------------------------
__global__ __launch_bounds__(T_) void setup_kernel(const int* __restrict__ src,
                                                   const int* __restrict__ token_lengths,
                                                   const int* __restrict__ token_len_p)
{
    __shared__ uint4 s_len4[T_ / 16];          // 128 bytes of lengths
    __shared__ unsigned short s_meta[T_];

    int b = blockIdx.x;
    int t = threadIdx.x;

    // Parallel gather phase.
    int s = src[t * B_ + b];
    int l = (s == 1) ? 0 : ((s == 0) ? 4 : token_lengths[s]);
    ((unsigned char*)s_len4)[t] = (unsigned char)l;
    s_meta[t] = 0;
    __syncthreads();

    if (t == 0) {
        int token_len = token_len_p ? token_len_p[0] : 20;

        // Bulk-load all 128 length bytes into registers (8x LDS.128).
        uint w[T_ / 4];
        #pragma unroll
        for (int i = 0; i < T_ / 16; i++) {
            uint4 v = s_len4[i];
            w[i * 4 + 0] = v.x; w[i * 4 + 1] = v.y;
            w[i * 4 + 2] = v.z; w[i * 4 + 3] = v.w;
        }

        int seg = 0, curr = 0, last_t = 0;
        #pragma unroll 8
        for (int tt = 0; tt < T_; tt++) {
            int ll = (w[tt >> 2] >> ((tt & 3) * 8)) & 0xFF;
            bool valid = (ll != 0);
            bool close = valid & (curr > 0) & (curr + ll > token_len);
            if (close) s_meta[last_t] |= (unsigned short)((seg + 1) << 1);
            seg  += (int)close;
            curr  = close ? 0 : curr;
            if (valid) s_meta[tt] |= 1;
            curr  += valid ? ll : 0;
            last_t = valid ? tt : last_t;
        }
        bool trail = (curr > 0);                 // open trailing segment
        if (trail) s_meta[last_t] |= (unsigned short)((seg + 1) << 1);
        seg += (int)trail;
        g_newlen[b] = seg;
    }
    __syncthreads();

    // Cooperative writeback of metadata.
    g_meta[b * T_ + t] = s_meta[t];
}

// ---------------------------------------------------------------------------
// Kernel 2 (fused data plane + rank): one block per SOURCE column b.
//   - Immediately issues PF=16 prefetch loads of the first embedding rows.
//   - Computes this column's stable descending rank bo over g_newlen
//     while those loads are in flight.
//   - Streams t = 0..127 with a 16-deep load pipeline, reading each input
//     row exactly once: accumulate valid rows, write-through rows t >= L,
//     flush the accumulator into out[seg] at segment-end flags.
// Traffic: 128 reads + 128 writes per column = 262 MB total.
// ---------------------------------------------------------------------------
__global__ __launch_bounds__(T_) void merge_kernel(const float4* __restrict__ embv,
                                                   float4* __restrict__ outv,
                                                   float* __restrict__ out_len,
                                                   int write_len)
{
    __shared__ unsigned short s_meta[T_];
    __shared__ int s_warp[4];
    __shared__ int s_rank;

    int b = blockIdx.x;
    int i = threadIdx.x;

    const long stride = (long)B_ * D4_;        // float4s per t-slab
    bool active = (i < D4_);
    int  ic     = active ? i : (D4_ - 1);      // clamped: loads always valid
    long ibase  = (long)b * D4_ + ic;

    // ---- kick off prefetch pipeline first (deep MLP) ----
    float4 buf[PF];
    #pragma unroll
    for (int k = 0; k < PF; k++) buf[k] = embv[ibase + (long)k * stride];

    // ---- overlap: meta load + rank reduction while loads are in flight ----
    s_meta[i] = g_meta[b * T_ + i];

    int myl = g_newlen[b];
    const int4* len4 = (const int4*)g_newlen;  // 512 / 4 = 128 == blockDim
    int4 v4 = len4[i];
    int j = 4 * i;
    int cnt = 0;
    cnt += (v4.x > myl) || (v4.x == myl && (j + 0) < b);
    cnt += (v4.y > myl) || (v4.y == myl && (j + 1) < b);
    cnt += (v4.z > myl) || (v4.z == myl && (j + 2) < b);
    cnt += (v4.w > myl) || (v4.w == myl && (j + 3) < b);
    #pragma unroll
    for (int o = 16; o > 0; o >>= 1) cnt += __shfl_down_sync(0xFFFFFFFFu, cnt, o);
    if ((i & 31) == 0) s_warp[i >> 5] = cnt;
    __syncthreads();
    if (i == 0) {
        int rank = s_warp[0] + s_warp[1] + s_warp[2] + s_warp[3];
        s_rank = rank;
        if (write_len) out_len[rank] = (float)myl;
    }
    __syncthreads();

    int  bo    = s_rank;
    int  L     = myl;
    long obase = (long)bo * D4_ + i;

    // ---- streaming loop with 16-deep ring buffer ----
    float4 acc = make_float4(0.f, 0.f, 0.f, 0.f);

    for (int to = 0; to < T_; to += PF) {
        #pragma unroll
        for (int k = 0; k < PF; k++) {
            int t = to + k;
            float4 v = buf[k];
            if (t + PF < T_)                       // refill slot (stays PF ahead)
                buf[k] = embv[ibase + (long)(t + PF) * stride];

            unsigned int m = s_meta[t];
            if (m & 1u) {
                acc.x += v.x; acc.y += v.y; acc.z += v.z; acc.w += v.w;
            }
            if (t >= L && active)
                outv[obase + (long)t * stride] = v;

            unsigned int e = m >> 1;
            if (e && active) {
                outv[obase + (long)((int)e - 1) * stride] = acc;
                acc = make_float4(0.f, 0.f, 0.f, 0.f);
            }
        }
    }
}

// ---------------------------------------------------------------------------
extern "C" void kernel_launch(void* const* d_in, const int* in_sizes, int n_in,
                              void* d_out, int out_size)
{
    const float* emb           = (const float*)d_in[0];   // (T,B,D) fp32
    const int*   src           = (const int*)d_in[1];     // (T,B) int32
    // d_in[2] = lengths (unused by reference computation)
    const int*   token_lengths = (const int*)d_in[3];     // (VOCAB,) int32
    const int*   token_len_p   = (n_in >= 5) ? (const int*)d_in[4] : nullptr;

    float* out = (float*)d_out;
    const long emb_elems = (long)T_ * B_ * D_;
    int write_len = (out_size >= emb_elems + B_) ? 1 : 0;

    setup_kernel<<<B_, T_>>>(src, token_lengths, token_len_p);
    merge_kernel<<<B_, T_>>>((const float4*)emb, (float4*)out,
                             out + emb_elems, write_len);
}

// round 8
// speedup vs baseline: 1.1258x; 1.1258x over previous
#include <cuda_runtime.h>
#include <cuda_bf16.h>

#define T_ 128
#define B_ 512
#define D_ 500
#define D4_ 125   // D/4 float4 per row
#define PF 8      // prefetch depth (rows ahead)

// Scratch (no allocation allowed).
__device__ int g_newlen[B_];
__device__ unsigned int g_arrive;   // zero-init; monotonic across graph replays

// ---------------------------------------------------------------------------
// Single fused kernel. One block per SOURCE column b, 128 threads.
//
//   Phase 0: issue PF=8 embedding prefetch loads immediately (deep MLP).
//   Phase 1: gather this column's token lengths (parallel), lane 0 runs the
//            branchless greedy scan -> s_meta + newlen; publish newlen.
//   Grid barrier: monotonic-counter spin (all 512 blocks provably co-resident
//            via __launch_bounds__(128,4): >=4 blocks/SM * 148 SMs = 592).
//            Target (arrived/512+1)*512 is replay-safe (no counter reset).
//   Phase 2: stable descending rank of this column over all newlens, then
//            stream t=0..127 with the 8-deep ring: read each input row ONCE,
//            accumulate valid rows, write-through rows t>=L, flush acc into
//            out[seg] at segment-end flags.  Traffic: 262 MB total.
// ---------------------------------------------------------------------------
__global__ __launch_bounds__(T_, 4) void fused_kernel(
    const float4* __restrict__ embv,
    const int*    __restrict__ src,
    const int*    __restrict__ token_lengths,
    const int*    __restrict__ token_len_p,
    float4*       __restrict__ outv,
    float*        __restrict__ out_len,
    int write_len)
{
    __shared__ unsigned short s_meta[T_];   // bit0=valid, bits[1:]=emit seg+1
    __shared__ unsigned char  s_len[T_];
    __shared__ int s_warp[4];
    __shared__ int s_rank;

    int b = blockIdx.x;
    int i = threadIdx.x;

    const long stride = (long)B_ * D4_;     // float4s per t-slab
    bool active = (i < D4_);
    int  ic     = active ? i : (D4_ - 1);   // clamped: loads always valid
    long ibase  = (long)b * D4_ + ic;

    // ---- Phase 0: kick off prefetch pipeline first ----
    float4 buf[PF];
    #pragma unroll
    for (int k = 0; k < PF; k++) buf[k] = embv[ibase + (long)k * stride];

    // ---- Phase 1: own-column gather + greedy scan (overlaps load latency) ----
    int s = src[i * B_ + b];
    int l = (s == 1) ? 0 : ((s == 0) ? 4 : token_lengths[s]);
    s_len[i]  = (unsigned char)l;
    s_meta[i] = 0;
    __syncthreads();

    if (i == 0) {
        int token_len = token_len_p ? token_len_p[0] : 20;

        const uint4* p4 = (const uint4*)s_len;
        uint w[T_ / 4];
        #pragma unroll
        for (int k = 0; k < T_ / 16; k++) {
            uint4 v = p4[k];
            w[k * 4 + 0] = v.x; w[k * 4 + 1] = v.y;
            w[k * 4 + 2] = v.z; w[k * 4 + 3] = v.w;
        }

        int seg = 0, curr = 0, last_t = 0;
        #pragma unroll
        for (int tt = 0; tt < T_; tt++) {
            int ll = (w[tt >> 2] >> ((tt & 3) * 8)) & 0xFF;
            bool valid = (ll != 0);
            bool close = valid & (curr > 0) & (curr + ll > token_len);
            if (close) s_meta[last_t] |= (unsigned short)((seg + 1) << 1);
            seg  += (int)close;
            curr  = close ? 0 : curr;
            if (valid) s_meta[tt] |= 1;
            curr  += valid ? ll : 0;
            last_t = valid ? tt : last_t;
        }
        bool trail = (curr > 0);
        if (trail) s_meta[last_t] |= (unsigned short)((seg + 1) << 1);
        seg += (int)trail;
        g_newlen[b] = seg;

        // ---- grid barrier (release: fence before arrive; acquire after) ----
        __threadfence();
        unsigned int arrived = atomicAdd(&g_arrive, 1u);
        unsigned int target  = (arrived / (unsigned)B_ + 1u) * (unsigned)B_;
        while (atomicAdd(&g_arrive, 0u) < target) __nanosleep(64);
        __threadfence();
    }
    __syncthreads();

    // ---- Phase 2: stable descending rank over all columns ----
    int myl = g_newlen[b];
    const int4* len4 = (const int4*)g_newlen;   // 512/4 = 128 == blockDim
    int4 v4 = __ldcg(&len4[i]);                 // bypass L1: cross-SM data
    int j = 4 * i;
    int cnt = 0;
    cnt += (v4.x > myl) || (v4.x == myl && (j + 0) < b);
    cnt += (v4.y > myl) || (v4.y == myl && (j + 1) < b);
    cnt += (v4.z > myl) || (v4.z == myl && (j + 2) < b);
    cnt += (v4.w > myl) || (v4.w == myl && (j + 3) < b);
    #pragma unroll
    for (int o = 16; o > 0; o >>= 1) cnt += __shfl_down_sync(0xFFFFFFFFu, cnt, o);
    if ((i & 31) == 0) s_warp[i >> 5] = cnt;
    __syncthreads();
    if (i == 0) {
        int rank = s_warp[0] + s_warp[1] + s_warp[2] + s_warp[3];
        s_rank = rank;
        if (write_len) out_len[rank] = (float)myl;
    }
    __syncthreads();

    int  bo    = s_rank;
    int  L     = myl;
    long obase = (long)bo * D4_ + i;

    // ---- streaming loop with 8-deep ring buffer ----
    float4 acc = make_float4(0.f, 0.f, 0.f, 0.f);

    for (int to = 0; to < T_; to += PF) {
        #pragma unroll
        for (int k = 0; k < PF; k++) {
            int t = to + k;
            float4 v = buf[k];
            if (t + PF < T_)                       // refill slot (stays PF ahead)
                buf[k] = embv[ibase + (long)(t + PF) * stride];

            unsigned int m = s_meta[t];
            if (m & 1u) {
                acc.x += v.x; acc.y += v.y; acc.z += v.z; acc.w += v.w;
            }
            if (t >= L && active)
                outv[obase + (long)t * stride] = v;

            unsigned int e = m >> 1;
            if (e && active) {
                outv[obase + (long)((int)e - 1) * stride] = acc;
                acc = make_float4(0.f, 0.f, 0.f, 0.f);
            }
        }
    }
}

// ---------------------------------------------------------------------------
extern "C" void kernel_launch(void* const* d_in, const int* in_sizes, int n_in,
                              void* d_out, int out_size)
{
    const float* emb           = (const float*)d_in[0];   // (T,B,D) fp32
    const int*   src           = (const int*)d_in[1];     // (T,B) int32
    // d_in[2] = lengths (unused by reference computation)
    const int*   token_lengths = (const int*)d_in[3];     // (VOCAB,) int32
    const int*   token_len_p   = (n_in >= 5) ? (const int*)d_in[4] : nullptr;

    float* out = (float*)d_out;
    const long emb_elems = (long)T_ * B_ * D_;
    int write_len = (out_size >= emb_elems + B_) ? 1 : 0;

    fused_kernel<<<B_, T_>>>((const float4*)emb, src, token_lengths, token_len_p,
                             (float4*)out, out + emb_elems, write_len);
}